// round 1
// baseline (speedup 1.0000x reference)
#include <cuda_runtime.h>

#define Bq   2
#define Fq   768
#define Lq   8192
#define IWq  3072
#define NFFT 16384

// ---------------- scratch (device globals; no allocations) ----------------
__device__ float  g_up[(size_t)Bq * Lq * IWq];       // 201 MB  up = u@w_in+b_in   [b][t][c]
__device__ float  g_v [(size_t)Bq * Fq * Lq];        // 50 MB   v (gated), then v2 [b][f][t]
__device__ float  g_x1[(size_t)Bq * Fq * Lq];        // 50 MB   x1 [b][f][t]
__device__ float  g_x2[(size_t)Bq * Fq * Lq];        // 50 MB   x2 [b][f][t]
__device__ float2 g_H [(size_t)2 * Fq * NFFT];       // 201 MB  FFT(h) per (order,f)

// ---------------- in-place radix-2 FFT on shared memory -------------------
// sign = -1: forward DFT; sign = +1: inverse butterflies (caller scales 1/N)
__device__ __forceinline__ void fft_smem(float* re, float* im, float sign) {
    const int tid = threadIdx.x;
    // bit reversal (14 bits)
    for (int i = tid; i < NFFT; i += 512) {
        int j = (int)(__brev((unsigned)i) >> 18);
        if (j > i) {
            float t;
            t = re[i]; re[i] = re[j]; re[j] = t;
            t = im[i]; im[i] = im[j]; im[j] = t;
        }
    }
    __syncthreads();
    #pragma unroll 1
    for (int s = 1; s <= 14; s++) {
        const int half = 1 << (s - 1);
        const float ang0 = sign * (6.28318530717958647692f / (float)(1 << s));
        for (int k = tid; k < NFFT / 2; k += 512) {
            int j  = k & (half - 1);
            int i1 = ((k >> (s - 1)) << s) + j;
            int i2 = i1 + half;
            float sn, cs;
            __sincosf(ang0 * (float)j, &sn, &cs);
            float ur = re[i1], ui = im[i1];
            float vr = re[i2], vi = im[i2];
            float tr = vr * cs - vi * sn;
            float ti = vr * sn + vi * cs;
            re[i1] = ur + tr; im[i1] = ui + ti;
            re[i2] = ur - tr; im[i2] = ui - ti;
        }
        __syncthreads();
    }
}

// ---------------- K1: up = u @ w_in + b_in   (M=16384,N=3072,K=768) -------
__global__ void __launch_bounds__(256) gemm_up(const float* __restrict__ A,
                                               const float* __restrict__ Bm,
                                               const float* __restrict__ bias) {
    __shared__ float As[8][128];
    __shared__ float Bs[8][128];
    const int m0 = blockIdx.y * 128, n0 = blockIdx.x * 128;
    const int tid = threadIdx.x;
    const int tx = tid & 15, ty = tid >> 4;
    float acc[8][8] = {};
    const int K = Fq;
    for (int k0 = 0; k0 < K; k0 += 8) {
        {   // A tile 128x8 (row-major A, ld=K)
            int am = tid >> 1, ak = (tid & 1) * 4;
            float4 av = *reinterpret_cast<const float4*>(&A[(size_t)(m0 + am) * K + k0 + ak]);
            As[ak + 0][am] = av.x; As[ak + 1][am] = av.y;
            As[ak + 2][am] = av.z; As[ak + 3][am] = av.w;
        }
        {   // B tile 8x128 (ld=IWq)
            int bk = tid >> 5, bn = (tid & 31) * 4;
            *reinterpret_cast<float4*>(&Bs[bk][bn]) =
                *reinterpret_cast<const float4*>(&Bm[(size_t)(k0 + bk) * IWq + n0 + bn]);
        }
        __syncthreads();
        #pragma unroll
        for (int kk = 0; kk < 8; kk++) {
            float a[8], b[8];
            #pragma unroll
            for (int i = 0; i < 8; i++) a[i] = As[kk][ty * 8 + i];
            #pragma unroll
            for (int j = 0; j < 8; j++) b[j] = Bs[kk][tx * 8 + j];
            #pragma unroll
            for (int i = 0; i < 8; i++)
                #pragma unroll
                for (int j = 0; j < 8; j++) acc[i][j] += a[i] * b[j];
        }
        __syncthreads();
    }
    float bb[8];
    #pragma unroll
    for (int j = 0; j < 8; j++) bb[j] = bias[n0 + tx * 8 + j];
    #pragma unroll
    for (int i = 0; i < 8; i++) {
        size_t row = (size_t)(m0 + ty * 8 + i);
        float4 w0 = make_float4(acc[i][0] + bb[0], acc[i][1] + bb[1], acc[i][2] + bb[2], acc[i][3] + bb[3]);
        float4 w1 = make_float4(acc[i][4] + bb[4], acc[i][5] + bb[5], acc[i][6] + bb[6], acc[i][7] + bb[7]);
        *reinterpret_cast<float4*>(&g_up[row * IWq + n0 + tx * 8 + 0]) = w0;
        *reinterpret_cast<float4*>(&g_up[row * IWq + n0 + tx * 8 + 4]) = w1;
    }
}

// ---------------- K2: depthwise conv(k=3,causal) + split + gate -----------
__global__ void conv_gate(const float* __restrict__ convk,
                          const float* __restrict__ convb) {
    int g = blockIdx.x * 256 + threadIdx.x;       // total B*L*F
    int f = g % Fq;
    int r = g / Fq;
    int t = r % Lq;
    int b = r / Lq;
    const float* uprow = g_up + (size_t)(b * Lq + t) * IWq;
    float out4[4];
    #pragma unroll
    for (int c4 = 0; c4 < 4; c4++) {
        int c = f + c4 * Fq;
        float k0 = convk[0 * IWq + c], k1 = convk[1 * IWq + c], k2 = convk[2 * IWq + c];
        float acc = convb[c] + k2 * uprow[c];
        if (t >= 1) acc += k1 * uprow[(ptrdiff_t)c - IWq];
        if (t >= 2) acc += k0 * uprow[(ptrdiff_t)c - 2 * IWq];
        out4[c4] = acc;
    }
    size_t o = (size_t)(b * Fq + f) * Lq + t;
    g_v [o] = out4[3] * out4[0];    // v * x0
    g_x1[o] = out4[1];
    g_x2[o] = out4[2];
}

// ---------------- K3: forward FFT of h per (order, feature) ---------------
__global__ void hfft_kernel(const float* __restrict__ h) {
    extern __shared__ float sm[];
    float* re = sm;
    float* im = sm + NFFT;
    const int of = blockIdx.x;           // o*Fq + f
    const int o = of / Fq, f = of % Fq;
    const int tid = threadIdx.x;
    for (int i = tid; i < NFFT; i += 512) {
        re[i] = (i < Lq) ? h[((size_t)o * Lq + i) * Fq + f] : 0.0f;
        im[i] = 0.0f;
    }
    __syncthreads();
    fft_smem(re, im, -1.0f);
    float2* Hf = g_H + (size_t)of * NFFT;
    for (int k = tid; k < NFFT; k += 512)
        Hf[k] = make_float2(re[k], im[k]);
}

// ---------------- K4: per-(b,f) chain: 2x (fftconv + gate) ----------------
__global__ void chain_kernel(const float* __restrict__ bias) {
    extern __shared__ float sm[];
    float* re = sm;
    float* im = sm + NFFT;
    const int bf = blockIdx.x;           // b*Fq + f
    const int f = bf % Fq;
    const int tid = threadIdx.x;
    const size_t base = (size_t)bf * Lq;

    float v[16];
    #pragma unroll
    for (int i = 0; i < 16; i++) v[i] = g_v[base + tid + i * 512];

    #pragma unroll 1
    for (int o = 0; o < 2; o++) {
        #pragma unroll
        for (int i = 0; i < 16; i++) {
            int p = tid + i * 512;
            re[p] = v[i];       im[p] = 0.0f;
            re[p + Lq] = 0.0f;  im[p + Lq] = 0.0f;
        }
        __syncthreads();
        fft_smem(re, im, -1.0f);
        const float2* Hf = g_H + (size_t)(o * Fq + f) * NFFT;
        for (int k = tid; k < NFFT; k += 512) {
            float2 hw = Hf[k];
            float xr = re[k], xi = im[k];
            re[k] = xr * hw.x - xi * hw.y;
            im[k] = xr * hw.y + xi * hw.x;
        }
        __syncthreads();
        fft_smem(re, im, 1.0f);
        const float bo = bias[o * Fq + f];
        const float* X = (o == 0 ? g_x1 : g_x2) + base;
        const float inv = 1.0f / (float)NFFT;
        #pragma unroll
        for (int i = 0; i < 16; i++) {
            int p = tid + i * 512;
            float y = re[p] * inv + v[i] * bo;
            v[i] = y * X[p];
        }
        __syncthreads();
    }
    #pragma unroll
    for (int i = 0; i < 16; i++) g_v[base + tid + i * 512] = v[i];
}

// ---------------- K5: out = v2 @ w_out + b_out  (M=16384,N=768,K=768) -----
// A(m,k) = g_v[b*Fq*Lq + k*Lq + t], m=(b,t); tiles never straddle b (Lq%128==0)
__global__ void __launch_bounds__(256) gemm_out(const float* __restrict__ Bm,
                                                const float* __restrict__ bias,
                                                float* __restrict__ out) {
    __shared__ float As[8][128];
    __shared__ float Bs[8][128];
    const int m0 = blockIdx.y * 128, n0 = blockIdx.x * 128;
    const int b = m0 / Lq, t0 = m0 % Lq;
    const float* A = g_v + (size_t)b * Fq * Lq;
    const int tid = threadIdx.x;
    const int tx = tid & 15, ty = tid >> 4;
    float acc[8][8] = {};
    for (int k0 = 0; k0 < Fq; k0 += 8) {
        {   // A tile: k-major source, contiguous in t
            int mm = (tid & 31) * 4, kk = tid >> 5;
            float4 av = *reinterpret_cast<const float4*>(&A[(size_t)(k0 + kk) * Lq + t0 + mm]);
            *reinterpret_cast<float4*>(&As[kk][mm]) = av;
        }
        {
            int bk = tid >> 5, bn = (tid & 31) * 4;
            *reinterpret_cast<float4*>(&Bs[bk][bn]) =
                *reinterpret_cast<const float4*>(&Bm[(size_t)(k0 + bk) * Fq + n0 + bn]);
        }
        __syncthreads();
        #pragma unroll
        for (int kk = 0; kk < 8; kk++) {
            float a[8], bb[8];
            #pragma unroll
            for (int i = 0; i < 8; i++) a[i] = As[kk][ty * 8 + i];
            #pragma unroll
            for (int j = 0; j < 8; j++) bb[j] = Bs[kk][tx * 8 + j];
            #pragma unroll
            for (int i = 0; i < 8; i++)
                #pragma unroll
                for (int j = 0; j < 8; j++) acc[i][j] += a[i] * bb[j];
        }
        __syncthreads();
    }
    float bb[8];
    #pragma unroll
    for (int j = 0; j < 8; j++) bb[j] = bias[n0 + tx * 8 + j];
    #pragma unroll
    for (int i = 0; i < 8; i++) {
        size_t row = (size_t)(m0 + ty * 8 + i);
        float4 w0 = make_float4(acc[i][0] + bb[0], acc[i][1] + bb[1], acc[i][2] + bb[2], acc[i][3] + bb[3]);
        float4 w1 = make_float4(acc[i][4] + bb[4], acc[i][5] + bb[5], acc[i][6] + bb[6], acc[i][7] + bb[7]);
        *reinterpret_cast<float4*>(&out[row * Fq + n0 + tx * 8 + 0]) = w0;
        *reinterpret_cast<float4*>(&out[row * Fq + n0 + tx * 8 + 4]) = w1;
    }
}

// ---------------- launch ---------------------------------------------------
extern "C" void kernel_launch(void* const* d_in, const int* in_sizes, int n_in,
                              void* d_out, int out_size) {
    const float* u      = (const float*)d_in[0];
    const float* h      = (const float*)d_in[1];
    const float* bias   = (const float*)d_in[2];
    const float* w_in   = (const float*)d_in[3];
    const float* b_in   = (const float*)d_in[4];
    const float* conv_k = (const float*)d_in[5];
    const float* conv_b = (const float*)d_in[6];
    const float* w_out  = (const float*)d_in[7];
    const float* b_out  = (const float*)d_in[8];
    float* out = (float*)d_out;

    const int smem = NFFT * 2 * sizeof(float);   // 131072
    cudaFuncSetAttribute(hfft_kernel,  cudaFuncAttributeMaxDynamicSharedMemorySize, smem);
    cudaFuncSetAttribute(chain_kernel, cudaFuncAttributeMaxDynamicSharedMemorySize, smem);

    // K1: up projection
    gemm_up<<<dim3(IWq / 128, (Bq * Lq) / 128), 256>>>(u, w_in, b_in);
    // K2: conv + split + gate (transposes to [b][f][t])
    conv_gate<<<(Bq * Lq * Fq) / 256, 256>>>(conv_k, conv_b);
    // K3: FFT of filters (can overlap with K1/K2 logically; same stream ok)
    hfft_kernel<<<2 * Fq, 512, smem>>>(h);
    // K4: the two fftconv + gate stages, one CTA per (b, f)
    chain_kernel<<<Bq * Fq, 512, smem>>>(bias);
    // K5: output projection
    gemm_out<<<dim3(Fq / 128, (Bq * Lq) / 128), 256>>>(w_out, b_out, out);
}

// round 2
// speedup vs baseline: 1.8516x; 1.8516x over previous
#include <cuda_runtime.h>
#include <cuda_bf16.h>
#include <cstdint>

#define Bq   2
#define Fq   768
#define Lq   8192
#define IWq  3072
#define NFFT 16384
#define Mq   (Bq * Lq)          // 16384
#define HSTR 8256               // padded half-spectrum stride (>= 8193)

// ---------------- scratch (device globals; no allocations) ----------------
__device__ float  g_up[(size_t)Mq * IWq];            // up = u@w_in+b_in  [m][c] f32
__device__ float  g_v [(size_t)Bq * Fq * Lq];        // gated v           [b][f][t]
__device__ float  g_x1[(size_t)Bq * Fq * Lq];
__device__ float  g_x2[(size_t)Bq * Fq * Lq];
__device__ float2 g_H [(size_t)2 * Fq * HSTR];       // half spectra of h, per (order,f)
__device__ __nv_bfloat16 g_uh [(size_t)Mq * Fq];     // u split hi/lo
__device__ __nv_bfloat16 g_ul [(size_t)Mq * Fq];
__device__ __nv_bfloat16 g_wih[(size_t)Fq * IWq];    // w_in split  [k][n]
__device__ __nv_bfloat16 g_wil[(size_t)Fq * IWq];
__device__ __nv_bfloat16 g_woh[(size_t)Fq * Fq];     // w_out split [k][n]
__device__ __nv_bfloat16 g_wol[(size_t)Fq * Fq];
__device__ __nv_bfloat16 g_vh [(size_t)Bq * Fq * Lq]; // chain output split [b][f][t]
__device__ __nv_bfloat16 g_vl [(size_t)Bq * Fq * Lq];

// ---------------- small helpers -------------------------------------------
__device__ __forceinline__ uint32_t cvta_s(const void* p) {
    return (uint32_t)__cvta_generic_to_shared(p);
}
__device__ __forceinline__ void ldsm_x4(uint32_t& r0, uint32_t& r1, uint32_t& r2, uint32_t& r3, uint32_t a) {
    asm volatile("ldmatrix.sync.aligned.m8n8.x4.shared.b16 {%0,%1,%2,%3}, [%4];\n"
                 : "=r"(r0), "=r"(r1), "=r"(r2), "=r"(r3) : "r"(a));
}
__device__ __forceinline__ void ldsm_x4_t(uint32_t& r0, uint32_t& r1, uint32_t& r2, uint32_t& r3, uint32_t a) {
    asm volatile("ldmatrix.sync.aligned.m8n8.x4.trans.shared.b16 {%0,%1,%2,%3}, [%4];\n"
                 : "=r"(r0), "=r"(r1), "=r"(r2), "=r"(r3) : "r"(a));
}
__device__ __forceinline__ void ldsm_x2_t(uint32_t& r0, uint32_t& r1, uint32_t a) {
    asm volatile("ldmatrix.sync.aligned.m8n8.x2.trans.shared.b16 {%0,%1}, [%2];\n"
                 : "=r"(r0), "=r"(r1) : "r"(a));
}
__device__ __forceinline__ void mma_bf16(float* d, const uint32_t* a, const uint32_t* b) {
    asm volatile("mma.sync.aligned.m16n8k16.row.col.f32.bf16.bf16.f32 "
                 "{%0,%1,%2,%3},{%4,%5,%6,%7},{%8,%9},{%0,%1,%2,%3};\n"
                 : "+f"(d[0]), "+f"(d[1]), "+f"(d[2]), "+f"(d[3])
                 : "r"(a[0]), "r"(a[1]), "r"(a[2]), "r"(a[3]), "r"(b[0]), "r"(b[1]));
}

// ---------------- split fp32 -> bf16 hi + bf16 lo --------------------------
__global__ void cvt_split(const float* __restrict__ s, __nv_bfloat16* __restrict__ hi,
                          __nv_bfloat16* __restrict__ lo, int n) {
    int i = blockIdx.x * 256 + threadIdx.x;
    if (i < n) {
        float x = s[i];
        __nv_bfloat16 h = __float2bfloat16(x);
        hi[i] = h;
        lo[i] = __float2bfloat16(x - __bfloat162float(h));
    }
}

// ---------------- in-place radix-2 FFT on shared memory -------------------
__device__ __forceinline__ void fft_smem(float* re, float* im, float sign) {
    const int tid = threadIdx.x;
    for (int i = tid; i < NFFT; i += 512) {
        int j = (int)(__brev((unsigned)i) >> 18);
        if (j > i) {
            float t;
            t = re[i]; re[i] = re[j]; re[j] = t;
            t = im[i]; im[i] = im[j]; im[j] = t;
        }
    }
    __syncthreads();
    #pragma unroll 1
    for (int s = 1; s <= 14; s++) {
        const int half = 1 << (s - 1);
        const float ang0 = sign * (6.28318530717958647692f / (float)(1 << s));
        for (int k = tid; k < NFFT / 2; k += 512) {
            int j  = k & (half - 1);
            int i1 = ((k >> (s - 1)) << s) + j;
            int i2 = i1 + half;
            float sn, cs;
            __sincosf(ang0 * (float)j, &sn, &cs);
            float ur = re[i1], ui = im[i1];
            float vr = re[i2], vi = im[i2];
            float tr = vr * cs - vi * sn;
            float ti = vr * sn + vi * cs;
            re[i1] = ur + tr; im[i1] = ui + ti;
            re[i2] = ur - tr; im[i2] = ui - ti;
        }
        __syncthreads();
    }
}

// ---------------- K1: up = u @ w_in + b_in (tensor cores, 3-term bf16) ----
__global__ void __launch_bounds__(256) gemm_up_tc(const float* __restrict__ bias) {
    __shared__ __align__(16) __nv_bfloat16 As[128 * 72];   // [m][k] ld=72
    __shared__ __align__(16) __nv_bfloat16 Bs[64 * 136];   // [k][n] ld=136
    const int m0 = blockIdx.y * 128, n0 = blockIdx.x * 128;
    const int tid = threadIdx.x, lane = tid & 31, wid = tid >> 5;
    const int wm = wid >> 2, wn = wid & 3;                  // 2 x 4 warps, warp tile 64x32
    float acc[4][4][4] = {};

    const __nv_bfloat16* Aseg[3] = { g_uh, g_ul, g_uh };
    const __nv_bfloat16* Bseg[3] = { g_wih, g_wih, g_wil };

    for (int seg = 0; seg < 3; seg++) {
        const __nv_bfloat16* Ap = Aseg[seg];
        const __nv_bfloat16* Bp = Bseg[seg];
        for (int kc = 0; kc < 12; kc++) {
            const int k0 = kc * 64;
            #pragma unroll
            for (int it = 0; it < 4; it++) {                // A tile 128x64
                int id = tid + it * 256, r = id >> 3, cu = id & 7;
                uint4 v = *(const uint4*)(Ap + (size_t)(m0 + r) * Fq + k0 + cu * 8);
                *(uint4*)(As + r * 72 + cu * 8) = v;
            }
            #pragma unroll
            for (int it = 0; it < 4; it++) {                // B tile 64x128
                int id = tid + it * 256, r = id >> 4, cu = id & 15;
                uint4 v = *(const uint4*)(Bp + (size_t)(k0 + r) * IWq + n0 + cu * 8);
                *(uint4*)(Bs + r * 136 + cu * 8) = v;
            }
            __syncthreads();
            #pragma unroll
            for (int ks = 0; ks < 4; ks++) {
                uint32_t a[4][4], bf[4][2];
                #pragma unroll
                for (int mi = 0; mi < 4; mi++) {
                    const __nv_bfloat16* p = As + (wm * 64 + mi * 16 + (lane & 15)) * 72
                                                + ks * 16 + (lane >> 4) * 8;
                    ldsm_x4(a[mi][0], a[mi][1], a[mi][2], a[mi][3], cvta_s(p));
                }
                #pragma unroll
                for (int ni = 0; ni < 4; ni++) {
                    const __nv_bfloat16* p = Bs + (ks * 16 + (lane & 15)) * 136
                                                + wn * 32 + ni * 8;
                    ldsm_x2_t(bf[ni][0], bf[ni][1], cvta_s(p));
                }
                #pragma unroll
                for (int mi = 0; mi < 4; mi++)
                    #pragma unroll
                    for (int ni = 0; ni < 4; ni++)
                        mma_bf16(acc[mi][ni], a[mi], bf[ni]);
            }
            __syncthreads();
        }
    }
    #pragma unroll
    for (int mi = 0; mi < 4; mi++)
        #pragma unroll
        for (int ni = 0; ni < 4; ni++) {
            int row = m0 + wm * 64 + mi * 16 + (lane >> 2);
            int col = n0 + wn * 32 + ni * 8 + (lane & 3) * 2;
            float b0 = bias[col], b1 = bias[col + 1];
            *(float2*)&g_up[(size_t)row * IWq + col] =
                make_float2(acc[mi][ni][0] + b0, acc[mi][ni][1] + b1);
            *(float2*)&g_up[(size_t)(row + 8) * IWq + col] =
                make_float2(acc[mi][ni][2] + b0, acc[mi][ni][3] + b1);
        }
}

// ---------------- K2: depthwise conv(k=3,causal) + split + gate -----------
__global__ void conv_gate(const float* __restrict__ convk,
                          const float* __restrict__ convb) {
    int g = blockIdx.x * 256 + threadIdx.x;
    int f = g % Fq;
    int r = g / Fq;
    int t = r % Lq;
    int b = r / Lq;
    const float* uprow = g_up + (size_t)(b * Lq + t) * IWq;
    float out4[4];
    #pragma unroll
    for (int c4 = 0; c4 < 4; c4++) {
        int c = f + c4 * Fq;
        float k0 = convk[0 * IWq + c], k1 = convk[1 * IWq + c], k2 = convk[2 * IWq + c];
        float acc = convb[c] + k2 * uprow[c];
        if (t >= 1) acc += k1 * uprow[(ptrdiff_t)c - IWq];
        if (t >= 2) acc += k0 * uprow[(ptrdiff_t)c - 2 * IWq];
        out4[c4] = acc;
    }
    size_t o = (size_t)(b * Fq + f) * Lq + t;
    g_v [o] = out4[3] * out4[0];
    g_x1[o] = out4[1];
    g_x2[o] = out4[2];
}

// ---------------- K3: packed FFT of h (order0 + i*order1, one per f) ------
__global__ void hfft_kernel(const float* __restrict__ h) {
    extern __shared__ float sm[];
    float* re = sm;
    float* im = sm + NFFT;
    const int f = blockIdx.x;
    const int tid = threadIdx.x;
    for (int i = tid; i < NFFT; i += 512) {
        re[i] = (i < Lq) ? h[(size_t)i * Fq + f] : 0.0f;
        im[i] = (i < Lq) ? h[(size_t)(Lq + i) * Fq + f] : 0.0f;
    }
    __syncthreads();
    fft_smem(re, im, -1.0f);
    float2* H0 = g_H + (size_t)f * HSTR;
    float2* H1 = g_H + (size_t)(Fq + f) * HSTR;
    for (int k = tid; k <= NFFT / 2; k += 512) {
        int m = (NFFT - k) & (NFFT - 1);
        float rk = re[k], ik = im[k], rm = re[m], imm = im[m];
        H0[k] = make_float2(0.5f * (rk + rm), 0.5f * (ik - imm));
        H1[k] = make_float2(0.5f * (ik + imm), 0.5f * (rm - rk));
    }
}

// ---------------- K4: per-(b, feature-pair) chain: 2x (fftconv + gate) ----
__global__ void chain_kernel(const float* __restrict__ bias) {
    extern __shared__ float sm[];
    float* re = sm;
    float* im = sm + NFFT;
    const int idx = blockIdx.x;                 // b * 384 + j
    const int b = idx / (Fq / 2), j = idx % (Fq / 2);
    const int f0 = 2 * j, f1 = f0 + 1;
    const int tid = threadIdx.x;
    const size_t base0 = ((size_t)b * Fq + f0) * Lq;
    const size_t base1 = base0 + Lq;

    float va[16], vb[16];
    #pragma unroll
    for (int i = 0; i < 16; i++) {
        va[i] = g_v[base0 + tid + i * 512];
        vb[i] = g_v[base1 + tid + i * 512];
    }

    #pragma unroll 1
    for (int o = 0; o < 2; o++) {
        #pragma unroll
        for (int i = 0; i < 16; i++) {
            int p = tid + i * 512;
            re[p] = va[i];      im[p] = vb[i];
            re[p + Lq] = 0.0f;  im[p + Lq] = 0.0f;
        }
        __syncthreads();
        fft_smem(re, im, -1.0f);

        const float2* H0 = g_H + ((size_t)o * Fq + f0) * HSTR;
        const float2* H1 = g_H + ((size_t)o * Fq + f1) * HSTR;
        for (int k = tid; k <= NFFT / 2; k += 512) {
            int m = (NFFT - k) & (NFFT - 1);
            float rk = re[k], ik = im[k], rm = re[m], imm = im[m];
            float Ar = 0.5f * (rk + rm),  Ai = 0.5f * (ik - imm);
            float Br = 0.5f * (ik + imm), Bi = 0.5f * (rm - rk);
            float2 h0 = H0[k], h1 = H1[k];
            float Yar = Ar * h0.x - Ai * h0.y, Yai = Ar * h0.y + Ai * h0.x;
            float Ybr = Br * h1.x - Bi * h1.y, Ybi = Br * h1.y + Bi * h1.x;
            re[k] = Yar - Ybi; im[k] = Yai + Ybr;
            if (m != k) { re[m] = Yar + Ybi; im[m] = Ybr - Yai; }
        }
        __syncthreads();
        fft_smem(re, im, 1.0f);

        const float bo0 = bias[o * Fq + f0], bo1 = bias[o * Fq + f1];
        const float* X0 = (o == 0 ? g_x1 : g_x2) + base0;
        const float* X1 = (o == 0 ? g_x1 : g_x2) + base1;
        const float inv = 1.0f / (float)NFFT;
        #pragma unroll
        for (int i = 0; i < 16; i++) {
            int p = tid + i * 512;
            va[i] = (re[p] * inv + va[i] * bo0) * X0[p];
            vb[i] = (im[p] * inv + vb[i] * bo1) * X1[p];
        }
        __syncthreads();
    }
    #pragma unroll
    for (int i = 0; i < 16; i++) {
        int p = tid + i * 512;
        float xa = va[i], xb = vb[i];
        __nv_bfloat16 ha = __float2bfloat16(xa);
        __nv_bfloat16 hb = __float2bfloat16(xb);
        g_vh[base0 + p] = ha;
        g_vl[base0 + p] = __float2bfloat16(xa - __bfloat162float(ha));
        g_vh[base1 + p] = hb;
        g_vl[base1 + p] = __float2bfloat16(xb - __bfloat162float(hb));
    }
}

// ---------------- K5: out = v2 @ w_out + b_out (tensor cores) -------------
// A source is k-major: A[m][k] = g_v*[b][k][t]; smem A kept [k][m], ldmatrix.trans
__global__ void __launch_bounds__(256) gemm_out_tc(const float* __restrict__ bias,
                                                   float* __restrict__ out) {
    __shared__ __align__(16) __nv_bfloat16 As[64 * 136];   // [k][m] ld=136
    __shared__ __align__(16) __nv_bfloat16 Bs[64 * 136];   // [k][n] ld=136
    const int m0 = blockIdx.y * 128, n0 = blockIdx.x * 128;
    const int b = m0 / Lq, t0 = m0 % Lq;
    const int tid = threadIdx.x, lane = tid & 31, wid = tid >> 5;
    const int wm = wid >> 2, wn = wid & 3;
    float acc[4][4][4] = {};

    const __nv_bfloat16* Aseg[3] = { g_vh, g_vl, g_vh };
    const __nv_bfloat16* Bseg[3] = { g_woh, g_woh, g_wol };
    const size_t abase = (size_t)b * Fq * Lq;

    for (int seg = 0; seg < 3; seg++) {
        const __nv_bfloat16* Ap = Aseg[seg] + abase;
        const __nv_bfloat16* Bp = Bseg[seg];
        for (int kc = 0; kc < 12; kc++) {
            const int k0 = kc * 64;
            #pragma unroll
            for (int it = 0; it < 4; it++) {                // A tile [k 64][t 128]
                int id = tid + it * 256, r = id >> 4, cu = id & 15;
                uint4 v = *(const uint4*)(Ap + (size_t)(k0 + r) * Lq + t0 + cu * 8);
                *(uint4*)(As + r * 136 + cu * 8) = v;
            }
            #pragma unroll
            for (int it = 0; it < 4; it++) {                // B tile [k 64][n 128]
                int id = tid + it * 256, r = id >> 4, cu = id & 15;
                uint4 v = *(const uint4*)(Bp + (size_t)(k0 + r) * Fq + n0 + cu * 8);
                *(uint4*)(Bs + r * 136 + cu * 8) = v;
            }
            __syncthreads();
            #pragma unroll
            for (int ks = 0; ks < 4; ks++) {
                uint32_t a[4][4], bf[4][2];
                #pragma unroll
                for (int mi = 0; mi < 4; mi++) {
                    // A fragment via trans: stored [k][m]
                    int krow = ks * 16 + ((lane >> 4) ? 8 : 0) + (lane & 7);
                    int mcol = wm * 64 + mi * 16 + ((lane >> 3) & 1) * 8;
                    const __nv_bfloat16* p = As + krow * 136 + mcol;
                    ldsm_x4_t(a[mi][0], a[mi][1], a[mi][2], a[mi][3], cvta_s(p));
                }
                #pragma unroll
                for (int ni = 0; ni < 4; ni++) {
                    const __nv_bfloat16* p = Bs + (ks * 16 + (lane & 15)) * 136
                                                + wn * 32 + ni * 8;
                    ldsm_x2_t(bf[ni][0], bf[ni][1], cvta_s(p));
                }
                #pragma unroll
                for (int mi = 0; mi < 4; mi++)
                    #pragma unroll
                    for (int ni = 0; ni < 4; ni++)
                        mma_bf16(acc[mi][ni], a[mi], bf[ni]);
            }
            __syncthreads();
        }
    }
    #pragma unroll
    for (int mi = 0; mi < 4; mi++)
        #pragma unroll
        for (int ni = 0; ni < 4; ni++) {
            int row = m0 + wm * 64 + mi * 16 + (lane >> 2);
            int col = n0 + wn * 32 + ni * 8 + (lane & 3) * 2;
            float b0 = bias[col], b1 = bias[col + 1];
            *(float2*)&out[(size_t)row * Fq + col] =
                make_float2(acc[mi][ni][0] + b0, acc[mi][ni][1] + b1);
            *(float2*)&out[(size_t)(row + 8) * Fq + col] =
                make_float2(acc[mi][ni][2] + b0, acc[mi][ni][3] + b1);
        }
}

// ---------------- launch ---------------------------------------------------
extern "C" void kernel_launch(void* const* d_in, const int* in_sizes, int n_in,
                              void* d_out, int out_size) {
    const float* u      = (const float*)d_in[0];
    const float* h      = (const float*)d_in[1];
    const float* bias   = (const float*)d_in[2];
    const float* w_in   = (const float*)d_in[3];
    const float* b_in   = (const float*)d_in[4];
    const float* conv_k = (const float*)d_in[5];
    const float* conv_b = (const float*)d_in[6];
    const float* w_out  = (const float*)d_in[7];
    const float* b_out  = (const float*)d_in[8];
    float* out = (float*)d_out;

    const int smem = NFFT * 2 * sizeof(float);   // 131072
    cudaFuncSetAttribute(hfft_kernel,  cudaFuncAttributeMaxDynamicSharedMemorySize, smem);
    cudaFuncSetAttribute(chain_kernel, cudaFuncAttributeMaxDynamicSharedMemorySize, smem);

    __nv_bfloat16 *uh, *ul, *wih, *wil, *woh, *wol;
    cudaGetSymbolAddress((void**)&uh,  g_uh);
    cudaGetSymbolAddress((void**)&ul,  g_ul);
    cudaGetSymbolAddress((void**)&wih, g_wih);
    cudaGetSymbolAddress((void**)&wil, g_wil);
    cudaGetSymbolAddress((void**)&woh, g_woh);
    cudaGetSymbolAddress((void**)&wol, g_wol);

    cvt_split<<<(Mq * Fq) / 256, 256>>>(u, uh, ul, Mq * Fq);
    cvt_split<<<(Fq * IWq) / 256, 256>>>(w_in, wih, wil, Fq * IWq);
    cvt_split<<<(Fq * Fq) / 256, 256>>>(w_out, woh, wol, Fq * Fq);

    gemm_up_tc<<<dim3(IWq / 128, Mq / 128), 256>>>(b_in);
    conv_gate<<<(Bq * Lq * Fq) / 256, 256>>>(conv_k, conv_b);
    hfft_kernel<<<Fq, 512, smem>>>(h);
    chain_kernel<<<Bq * Fq / 2, 512, smem>>>(bias);
    gemm_out_tc<<<dim3(Fq / 128, Mq / 128), 256>>>(b_out, out);
}

// round 3
// speedup vs baseline: 3.1758x; 1.7152x over previous
#include <cuda_runtime.h>
#include <cuda_bf16.h>
#include <cstdint>

#define Bq   2
#define Fq   768
#define Lq   8192
#define IWq  3072
#define NFFT 16384
#define Mq   (Bq * Lq)          // 16384
#define HSTR 8256               // padded half-spectrum stride (>= 8193)

// ---------------- scratch (device globals; no allocations) ----------------
__device__ __align__(16) float  g_up[(size_t)Mq * IWq];
__device__ __align__(16) float  g_v [(size_t)Bq * Fq * Lq];   // [b][f][t]
__device__ __align__(16) float  g_x1[(size_t)Bq * Fq * Lq];
__device__ __align__(16) float  g_x2[(size_t)Bq * Fq * Lq];
__device__ __align__(16) float  g_ht[(size_t)2 * Fq * Lq];    // h transposed [o][f][t]
__device__ __align__(16) float2 g_H [(size_t)2 * Fq * HSTR];  // half spectra of h
__device__ __align__(16) __nv_bfloat16 g_uh [(size_t)Mq * Fq];
__device__ __align__(16) __nv_bfloat16 g_ul [(size_t)Mq * Fq];
__device__ __align__(16) __nv_bfloat16 g_wih[(size_t)Fq * IWq];
__device__ __align__(16) __nv_bfloat16 g_wil[(size_t)Fq * IWq];
__device__ __align__(16) __nv_bfloat16 g_woh[(size_t)Fq * Fq];
__device__ __align__(16) __nv_bfloat16 g_wol[(size_t)Fq * Fq];
__device__ __align__(16) __nv_bfloat16 g_vh [(size_t)Bq * Fq * Lq];
__device__ __align__(16) __nv_bfloat16 g_vl [(size_t)Bq * Fq * Lq];

// ---------------- helpers ---------------------------------------------------
__device__ __forceinline__ uint32_t cvta_s(const void* p) {
    return (uint32_t)__cvta_generic_to_shared(p);
}
__device__ __forceinline__ void cp16(uint32_t dst, const void* src) {
    asm volatile("cp.async.cg.shared.global [%0], [%1], 16;\n" :: "r"(dst), "l"(src));
}
__device__ __forceinline__ void cp_commit() { asm volatile("cp.async.commit_group;\n"); }
__device__ __forceinline__ void cp_wait1()  { asm volatile("cp.async.wait_group 1;\n"); }
__device__ __forceinline__ void cp_wait0()  { asm volatile("cp.async.wait_group 0;\n"); }

__device__ __forceinline__ void ldsm_x4(uint32_t& r0, uint32_t& r1, uint32_t& r2, uint32_t& r3, uint32_t a) {
    asm volatile("ldmatrix.sync.aligned.m8n8.x4.shared.b16 {%0,%1,%2,%3}, [%4];\n"
                 : "=r"(r0), "=r"(r1), "=r"(r2), "=r"(r3) : "r"(a));
}
__device__ __forceinline__ void ldsm_x4_t(uint32_t& r0, uint32_t& r1, uint32_t& r2, uint32_t& r3, uint32_t a) {
    asm volatile("ldmatrix.sync.aligned.m8n8.x4.trans.shared.b16 {%0,%1,%2,%3}, [%4];\n"
                 : "=r"(r0), "=r"(r1), "=r"(r2), "=r"(r3) : "r"(a));
}
__device__ __forceinline__ void ldsm_x2_t(uint32_t& r0, uint32_t& r1, uint32_t a) {
    asm volatile("ldmatrix.sync.aligned.m8n8.x2.trans.shared.b16 {%0,%1}, [%2];\n"
                 : "=r"(r0), "=r"(r1) : "r"(a));
}
__device__ __forceinline__ void mma_bf16(float* d, const uint32_t* a, const uint32_t* b) {
    asm volatile("mma.sync.aligned.m16n8k16.row.col.f32.bf16.bf16.f32 "
                 "{%0,%1,%2,%3},{%4,%5,%6,%7},{%8,%9},{%0,%1,%2,%3};\n"
                 : "+f"(d[0]), "+f"(d[1]), "+f"(d[2]), "+f"(d[3])
                 : "r"(a[0]), "r"(a[1]), "r"(a[2]), "r"(a[3]), "r"(b[0]), "r"(b[1]));
}

// ---------------- split fp32 -> bf16 hi + lo --------------------------------
__global__ void cvt_split(const float* __restrict__ s, __nv_bfloat16* __restrict__ hi,
                          __nv_bfloat16* __restrict__ lo, int n) {
    int i = blockIdx.x * 256 + threadIdx.x;
    if (i < n) {
        float x = s[i];
        __nv_bfloat16 h = __float2bfloat16(x);
        hi[i] = h;
        lo[i] = __float2bfloat16(x - __bfloat162float(h));
    }
}

// ---------------- register FFT machinery ------------------------------------
// W32C[j] = cos(2*pi*j/32), W32S[j] = -sin(2*pi*j/32)   (forward twiddles)
__device__ __constant__ float W32C[16] = {
    1.0f, 0.9807852804032304f, 0.9238795325112867f, 0.8314696123025452f,
    0.7071067811865476f, 0.5555702330196022f, 0.3826834323650898f, 0.19509032201612825f,
    0.0f, -0.19509032201612825f, -0.3826834323650898f, -0.5555702330196022f,
    -0.7071067811865476f, -0.8314696123025452f, -0.9238795325112867f, -0.9807852804032304f };
__device__ __constant__ float W32S[16] = {
    0.0f, -0.19509032201612825f, -0.3826834323650898f, -0.5555702330196022f,
    -0.7071067811865476f, -0.8314696123025452f, -0.9238795325112867f, -0.9807852804032304f,
    -1.0f, -0.9807852804032304f, -0.9238795325112867f, -0.8314696123025452f,
    -0.7071067811865476f, -0.5555702330196022f, -0.3826834323650898f, -0.19509032201612825f };

#define SWAPC(a, b) { float t_ = xr[a]; xr[a] = xr[b]; xr[b] = t_; \
                      t_ = xi[a]; xi[a] = xi[b]; xi[b] = t_; }

// DIR = -1 forward, +1 inverse
template<int DIR>
__device__ __forceinline__ void fft32r(float* xr, float* xi) {
    SWAPC(1,16)  SWAPC(2,8)   SWAPC(3,24)  SWAPC(5,20)
    SWAPC(6,12)  SWAPC(7,28)  SWAPC(9,18)  SWAPC(11,26)
    SWAPC(13,22) SWAPC(15,30) SWAPC(19,25) SWAPC(23,29)
    #pragma unroll
    for (int s = 1; s <= 5; s++) {
        const int half = 1 << (s - 1);
        #pragma unroll
        for (int k = 0; k < 16; k++) {
            int j  = k & (half - 1);
            int i1 = ((k >> (s - 1)) << s) + j;
            int i2 = i1 + half;
            int w  = j * (32 >> s);
            float cs = W32C[w];
            float sn = (DIR < 0) ? W32S[w] : -W32S[w];
            float tr = xr[i2] * cs - xi[i2] * sn;
            float ti = xr[i2] * sn + xi[i2] * cs;
            xr[i2] = xr[i1] - tr; xi[i2] = xi[i1] - ti;
            xr[i1] += tr;         xi[i1] += ti;
        }
    }
}

template<int DIR>
__device__ __forceinline__ void fft16r(float* xr, float* xi) {
    SWAPC(1,8) SWAPC(2,4) SWAPC(3,12) SWAPC(5,10) SWAPC(7,14) SWAPC(11,13)
    #pragma unroll
    for (int s = 1; s <= 4; s++) {
        const int half = 1 << (s - 1);
        #pragma unroll
        for (int k = 0; k < 8; k++) {
            int j  = k & (half - 1);
            int i1 = ((k >> (s - 1)) << s) + j;
            int i2 = i1 + half;
            int w  = j * (32 >> s);
            float cs = W32C[w];
            float sn = (DIR < 0) ? W32S[w] : -W32S[w];
            float tr = xr[i2] * cs - xi[i2] * sn;
            float ti = xr[i2] * sn + xi[i2] * cs;
            xr[i2] = xr[i1] - tr; xi[i2] = xi[i1] - ti;
            xr[i1] += tr;         xi[i1] += ti;
        }
    }
}
#undef SWAPC

// Full 16384-pt FFT: input in regs xr/xi (xr[n1] = x[n1*512 + tid]); output
// natural-order in RE/IM. 3 passes: 32 (regs) x 32 (regs) x 16 (regs) with
// conflict-free padded smem exchanges. DIR=-1 fwd, +1 inv (unnormalized).
template<int DIR>
__device__ __forceinline__ void fft16k(float* RE, float* IM, float* xr, float* xi, int tid) {
    const float TW = (DIR < 0) ? -6.2831853071795864769f : 6.2831853071795864769f;
    // ---- pass 1: FFT32 over n1, twiddle W_N^(tid*k1), store z[k1*528 + tid]
    fft32r<DIR>(xr, xi);
    {
        float s1, c1;
        sincosf(TW * (float)tid * (1.0f / 16384.0f), &s1, &c1);
        RE[tid] = xr[0]; IM[tid] = xi[0];
        float cr = c1, ci = s1;
        #pragma unroll
        for (int k1 = 1; k1 < 32; k1++) {
            RE[k1 * 528 + tid] = xr[k1] * cr - xi[k1] * ci;
            IM[k1 * 528 + tid] = xr[k1] * ci + xi[k1] * cr;
            float nr = cr * c1 - ci * s1;
            ci = cr * s1 + ci * c1; cr = nr;
        }
    }
    __syncthreads();
    // ---- pass 2: FFT32 over m1, twiddle W_512^(m2*j1), store w[j1*544+k1*17+m2]
    {
        int k1 = tid >> 4, m2 = tid & 15;
        #pragma unroll
        for (int m1 = 0; m1 < 32; m1++) {
            xr[m1] = RE[k1 * 528 + m1 * 16 + m2];
            xi[m1] = IM[k1 * 528 + m1 * 16 + m2];
        }
        __syncthreads();
        fft32r<DIR>(xr, xi);
        float s1, c1;
        sincosf(TW * (float)m2 * (1.0f / 512.0f), &s1, &c1);
        int wb = k1 * 17 + m2;
        RE[wb] = xr[0]; IM[wb] = xi[0];
        float cr = c1, ci = s1;
        #pragma unroll
        for (int j1 = 1; j1 < 32; j1++) {
            RE[j1 * 544 + wb] = xr[j1] * cr - xi[j1] * ci;
            IM[j1 * 544 + wb] = xr[j1] * ci + xi[j1] * cr;
            float nr = cr * c1 - ci * s1;
            ci = cr * s1 + ci * c1; cr = nr;
        }
    }
    __syncthreads();
    // ---- pass 3: FFT16 over m2, out[k1 + 32*j1 + 1024*j2]
    {
        int k1 = tid & 31, j1 = tid >> 5;    // j1 in [0,16); also j1+16
        #pragma unroll
        for (int m2 = 0; m2 < 16; m2++) {
            xr[m2]      = RE[j1 * 544 + k1 * 17 + m2];
            xi[m2]      = IM[j1 * 544 + k1 * 17 + m2];
            xr[16 + m2] = RE[(j1 + 16) * 544 + k1 * 17 + m2];
            xi[16 + m2] = IM[(j1 + 16) * 544 + k1 * 17 + m2];
        }
        __syncthreads();
        fft16r<DIR>(xr, xi);
        fft16r<DIR>(xr + 16, xi + 16);
        #pragma unroll
        for (int j2 = 0; j2 < 16; j2++) {
            RE[k1 + 32 * j1 + 1024 * j2] = xr[j2];
            IM[k1 + 32 * j1 + 1024 * j2] = xi[j2];
            RE[k1 + 32 * (j1 + 16) + 1024 * j2] = xr[16 + j2];
            IM[k1 + 32 * (j1 + 16) + 1024 * j2] = xi[16 + j2];
        }
    }
    __syncthreads();
}

#define FFT_SMEM_FLOATS 17408          // max(z:16896, w:17408, spectrum:16384)

// ---------------- K1: up = u @ w_in + b_in (tensor cores, cp.async x2buf) --
__device__ __forceinline__ void up_loadA(__nv_bfloat16* dst, const __nv_bfloat16* Ap,
                                         int m0, int k0, int tid) {
    #pragma unroll
    for (int it = 0; it < 4; it++) {
        int id = tid + it * 256, r = id >> 3, cu = id & 7;
        cp16(cvta_s(dst + r * 72 + cu * 8), Ap + (size_t)(m0 + r) * Fq + k0 + cu * 8);
    }
}
__device__ __forceinline__ void up_loadB(__nv_bfloat16* dst, const __nv_bfloat16* Bp,
                                         int n0, int k0, int tid) {
    #pragma unroll
    for (int it = 0; it < 4; it++) {
        int id = tid + it * 256, r = id >> 4, cu = id & 15;
        cp16(cvta_s(dst + r * 136 + cu * 8), Bp + (size_t)(k0 + r) * IWq + n0 + cu * 8);
    }
}

__global__ void __launch_bounds__(256) gemm_up_tc(const float* __restrict__ bias) {
    extern __shared__ __align__(16) __nv_bfloat16 smp[];
    __nv_bfloat16* As = smp;                 // 2 x 128*72
    __nv_bfloat16* Bs = smp + 2 * 9216;      // 2 x 64*136
    const int m0 = blockIdx.y * 128, n0 = blockIdx.x * 128;
    const int tid = threadIdx.x, lane = tid & 31, wid = tid >> 5;
    const int wm = wid >> 2, wn = wid & 3;
    float acc[4][4][4] = {};

    const __nv_bfloat16* Aseg[3] = { g_uh, g_ul, g_uh };
    const __nv_bfloat16* Bseg[3] = { g_wih, g_wih, g_wil };

    up_loadA(As, Aseg[0], m0, 0, tid);
    up_loadB(Bs, Bseg[0], n0, 0, tid);
    cp_commit();

    for (int st = 0; st < 36; st++) {
        int nst = st + 1;
        if (nst < 36) {
            int sg = nst / 12, kc = nst % 12;
            up_loadA(As + (nst & 1) * 9216, Aseg[sg], m0, kc * 64, tid);
            up_loadB(Bs + (nst & 1) * 8704, Bseg[sg], n0, kc * 64, tid);
            cp_commit();
            cp_wait1();
        } else {
            cp_wait0();
        }
        __syncthreads();
        const __nv_bfloat16* Ab = As + (st & 1) * 9216;
        const __nv_bfloat16* Bb = Bs + (st & 1) * 8704;
        #pragma unroll
        for (int ks = 0; ks < 4; ks++) {
            uint32_t a[4][4], bf[4][2];
            #pragma unroll
            for (int mi = 0; mi < 4; mi++) {
                const __nv_bfloat16* p = Ab + (wm * 64 + mi * 16 + (lane & 15)) * 72
                                            + ks * 16 + (lane >> 4) * 8;
                ldsm_x4(a[mi][0], a[mi][1], a[mi][2], a[mi][3], cvta_s(p));
            }
            #pragma unroll
            for (int ni = 0; ni < 4; ni++) {
                const __nv_bfloat16* p = Bb + (ks * 16 + (lane & 15)) * 136
                                            + wn * 32 + ni * 8;
                ldsm_x2_t(bf[ni][0], bf[ni][1], cvta_s(p));
            }
            #pragma unroll
            for (int mi = 0; mi < 4; mi++)
                #pragma unroll
                for (int ni = 0; ni < 4; ni++)
                    mma_bf16(acc[mi][ni], a[mi], bf[ni]);
        }
        __syncthreads();
    }
    #pragma unroll
    for (int mi = 0; mi < 4; mi++)
        #pragma unroll
        for (int ni = 0; ni < 4; ni++) {
            int row = m0 + wm * 64 + mi * 16 + (lane >> 2);
            int col = n0 + wn * 32 + ni * 8 + (lane & 3) * 2;
            float b0 = bias[col], b1 = bias[col + 1];
            *(float2*)&g_up[(size_t)row * IWq + col] =
                make_float2(acc[mi][ni][0] + b0, acc[mi][ni][1] + b1);
            *(float2*)&g_up[(size_t)(row + 8) * IWq + col] =
                make_float2(acc[mi][ni][2] + b0, acc[mi][ni][3] + b1);
        }
}

// ---------------- K2: depthwise conv + split + gate (tiled transpose) -----
__global__ void __launch_bounds__(256) conv_gate(const float* __restrict__ convk,
                                                 const float* __restrict__ convb) {
    __shared__ float s_in[34 * 4 * 32];
    __shared__ float s_out[3][32][33];
    const int f0 = blockIdx.x * 32, t0 = blockIdx.y * 32, b = blockIdx.z;
    const int tid = threadIdx.x, tx = tid & 31, ty = tid >> 5;

    for (int r = ty; r < 136; r += 8) {
        int tt = r >> 2, c4 = r & 3;
        int t = t0 - 2 + tt;
        float v = 0.0f;
        if (t >= 0)
            v = g_up[(size_t)(b * Lq + t) * IWq + c4 * Fq + f0 + tx];
        s_in[(tt * 4 + c4) * 32 + tx] = v;
    }
    float kk[4][3], cb[4];
    #pragma unroll
    for (int c4 = 0; c4 < 4; c4++) {
        int c = c4 * Fq + f0 + tx;
        kk[c4][0] = convk[c]; kk[c4][1] = convk[IWq + c]; kk[c4][2] = convk[2 * IWq + c];
        cb[c4] = convb[c];
    }
    __syncthreads();
    #pragma unroll
    for (int q = 0; q < 4; q++) {
        int ts = ty + 8 * q;
        float o[4];
        #pragma unroll
        for (int c4 = 0; c4 < 4; c4++)
            o[c4] = cb[c4]
                  + kk[c4][2] * s_in[((ts + 2) * 4 + c4) * 32 + tx]
                  + kk[c4][1] * s_in[((ts + 1) * 4 + c4) * 32 + tx]
                  + kk[c4][0] * s_in[((ts    ) * 4 + c4) * 32 + tx];
        s_out[0][tx][ts] = o[3] * o[0];
        s_out[1][tx][ts] = o[1];
        s_out[2][tx][ts] = o[2];
    }
    __syncthreads();
    float* dst[3] = { g_v, g_x1, g_x2 };
    #pragma unroll
    for (int jn = 0; jn < 3; jn++)
        #pragma unroll
        for (int qq = 0; qq < 4; qq++) {
            int fr = ty + 8 * qq;
            dst[jn][(size_t)(b * Fq + f0 + fr) * Lq + t0 + tx] = s_out[jn][fr][tx];
        }
}

// ---------------- K2b: transpose h to [o][f][t] ----------------------------
__global__ void transpose_h(const float* __restrict__ h) {
    __shared__ float tile[32][33];
    const int f0 = blockIdx.x * 32, t0 = blockIdx.y * 32, o = blockIdx.z;
    const int tx = threadIdx.x, ty = threadIdx.y;
    for (int r = ty; r < 32; r += 8)
        tile[r][tx] = h[((size_t)o * Lq + t0 + r) * Fq + f0 + tx];
    __syncthreads();
    for (int r = ty; r < 32; r += 8)
        g_ht[((size_t)(o * Fq + f0 + r)) * Lq + t0 + tx] = tile[tx][r];
}

// ---------------- K3: packed FFT of h (order0 + i*order1) ------------------
__global__ void __launch_bounds__(512) hfft_kernel() {
    extern __shared__ float sm[];
    float* RE = sm;
    float* IM = sm + FFT_SMEM_FLOATS;
    const int f = blockIdx.x, tid = threadIdx.x;
    const float* h0 = g_ht + (size_t)f * Lq;
    const float* h1 = g_ht + (size_t)(Fq + f) * Lq;
    float xr[32], xi[32];
    #pragma unroll
    for (int n1 = 0; n1 < 32; n1++) {
        int p = n1 * 512 + tid;
        xr[n1] = (n1 < 16) ? h0[p] : 0.0f;
        xi[n1] = (n1 < 16) ? h1[p] : 0.0f;
    }
    fft16k<-1>(RE, IM, xr, xi, tid);
    float2* H0 = g_H + (size_t)f * HSTR;
    float2* H1 = g_H + (size_t)(Fq + f) * HSTR;
    for (int k = tid; k <= NFFT / 2; k += 512) {
        int m = (NFFT - k) & (NFFT - 1);
        float rk = RE[k], ik = IM[k], rm = RE[m], imm = IM[m];
        H0[k] = make_float2(0.5f * (rk + rm), 0.5f * (ik - imm));
        H1[k] = make_float2(0.5f * (ik + imm), 0.5f * (rm - rk));
    }
}

// ---------------- K4: per-(b, feature-pair) chain ---------------------------
__global__ void __launch_bounds__(512) chain_kernel(const float* __restrict__ bias) {
    extern __shared__ float sm[];
    float* RE = sm;
    float* IM = sm + FFT_SMEM_FLOATS;
    const int idx = blockIdx.x;
    const int b = idx / (Fq / 2), j = idx % (Fq / 2);
    const int f0 = 2 * j, f1 = f0 + 1;
    const int tid = threadIdx.x;
    const size_t base0 = ((size_t)b * Fq + f0) * Lq;
    const size_t base1 = base0 + Lq;
    const float inv = 1.0f / (float)NFFT;
    float xr[32], xi[32];

    #pragma unroll 1
    for (int o = 0; o < 2; o++) {
        #pragma unroll
        for (int n1 = 0; n1 < 32; n1++) {
            int p = n1 * 512 + tid;
            xr[n1] = (n1 < 16) ? g_v[base0 + p] : 0.0f;
            xi[n1] = (n1 < 16) ? g_v[base1 + p] : 0.0f;
        }
        __syncthreads();
        fft16k<-1>(RE, IM, xr, xi, tid);

        const float2* H0 = g_H + ((size_t)o * Fq + f0) * HSTR;
        const float2* H1 = g_H + ((size_t)o * Fq + f1) * HSTR;
        for (int k = tid; k <= NFFT / 2; k += 512) {
            int m = (NFFT - k) & (NFFT - 1);
            float rk = RE[k], ik = IM[k], rm = RE[m], imm = IM[m];
            float Ar = 0.5f * (rk + rm),  Ai = 0.5f * (ik - imm);
            float Br = 0.5f * (ik + imm), Bi = 0.5f * (rm - rk);
            float2 h0 = H0[k], h1 = H1[k];
            float Yar = Ar * h0.x - Ai * h0.y, Yai = Ar * h0.y + Ai * h0.x;
            float Ybr = Br * h1.x - Bi * h1.y, Ybi = Br * h1.y + Bi * h1.x;
            RE[k] = Yar - Ybi; IM[k] = Yai + Ybr;
            if (m != k) { RE[m] = Yar + Ybi; IM[m] = Ybr - Yai; }
        }
        __syncthreads();
        #pragma unroll
        for (int n1 = 0; n1 < 32; n1++) {
            int p = n1 * 512 + tid;
            xr[n1] = RE[p]; xi[n1] = IM[p];
        }
        __syncthreads();
        fft16k<1>(RE, IM, xr, xi, tid);

        const float bo0 = bias[o * Fq + f0], bo1 = bias[o * Fq + f1];
        const float* X0 = (o == 0 ? g_x1 : g_x2) + base0;
        const float* X1 = (o == 0 ? g_x1 : g_x2) + base1;
        if (o == 0) {
            #pragma unroll
            for (int i = 0; i < 16; i++) {
                int p = tid + i * 512;
                float v0 = g_v[base0 + p], v1 = g_v[base1 + p];
                g_v[base0 + p] = (RE[p] * inv + v0 * bo0) * X0[p];
                g_v[base1 + p] = (IM[p] * inv + v1 * bo1) * X1[p];
            }
        } else {
            #pragma unroll
            for (int i = 0; i < 16; i++) {
                int p = tid + i * 512;
                float v0 = g_v[base0 + p], v1 = g_v[base1 + p];
                float y0 = (RE[p] * inv + v0 * bo0) * X0[p];
                float y1 = (IM[p] * inv + v1 * bo1) * X1[p];
                __nv_bfloat16 h0 = __float2bfloat16(y0);
                __nv_bfloat16 h1 = __float2bfloat16(y1);
                g_vh[base0 + p] = h0;
                g_vl[base0 + p] = __float2bfloat16(y0 - __bfloat162float(h0));
                g_vh[base1 + p] = h1;
                g_vl[base1 + p] = __float2bfloat16(y1 - __bfloat162float(h1));
            }
        }
        __syncthreads();
    }
}

// ---------------- K5: out = v2 @ w_out + b_out ------------------------------
__device__ __forceinline__ void out_loadA(__nv_bfloat16* dst, const __nv_bfloat16* Ap,
                                          int t0, int k0, int tid) {
    #pragma unroll
    for (int it = 0; it < 4; it++) {
        int id = tid + it * 256, r = id >> 4, cu = id & 15;
        cp16(cvta_s(dst + r * 136 + cu * 8), Ap + (size_t)(k0 + r) * Lq + t0 + cu * 8);
    }
}
__device__ __forceinline__ void out_loadB(__nv_bfloat16* dst, const __nv_bfloat16* Bp,
                                          int n0, int k0, int tid) {
    #pragma unroll
    for (int it = 0; it < 4; it++) {
        int id = tid + it * 256, r = id >> 4, cu = id & 15;
        cp16(cvta_s(dst + r * 136 + cu * 8), Bp + (size_t)(k0 + r) * Fq + n0 + cu * 8);
    }
}

__global__ void __launch_bounds__(256) gemm_out_tc(const float* __restrict__ bias,
                                                   float* __restrict__ out) {
    extern __shared__ __align__(16) __nv_bfloat16 smp[];
    __nv_bfloat16* As = smp;                  // 2 x 64*136
    __nv_bfloat16* Bs = smp + 2 * 8704;       // 2 x 64*136
    const int m0 = blockIdx.y * 128, n0 = blockIdx.x * 128;
    const int b = m0 / Lq, t0 = m0 % Lq;
    const int tid = threadIdx.x, lane = tid & 31, wid = tid >> 5;
    const int wm = wid >> 2, wn = wid & 3;
    float acc[4][4][4] = {};

    const size_t abase = (size_t)b * Fq * Lq;
    const __nv_bfloat16* Aseg[3] = { g_vh + abase, g_vl + abase, g_vh + abase };
    const __nv_bfloat16* Bseg[3] = { g_woh, g_woh, g_wol };

    out_loadA(As, Aseg[0], t0, 0, tid);
    out_loadB(Bs, Bseg[0], n0, 0, tid);
    cp_commit();

    for (int st = 0; st < 36; st++) {
        int nst = st + 1;
        if (nst < 36) {
            int sg = nst / 12, kc = nst % 12;
            out_loadA(As + (nst & 1) * 8704, Aseg[sg], t0, kc * 64, tid);
            out_loadB(Bs + (nst & 1) * 8704, Bseg[sg], n0, kc * 64, tid);
            cp_commit();
            cp_wait1();
        } else {
            cp_wait0();
        }
        __syncthreads();
        const __nv_bfloat16* Ab = As + (st & 1) * 8704;
        const __nv_bfloat16* Bb = Bs + (st & 1) * 8704;
        #pragma unroll
        for (int ks = 0; ks < 4; ks++) {
            uint32_t a[4][4], bf[4][2];
            #pragma unroll
            for (int mi = 0; mi < 4; mi++) {
                int krow = ks * 16 + ((lane >> 4) ? 8 : 0) + (lane & 7);
                int mcol = wm * 64 + mi * 16 + ((lane >> 3) & 1) * 8;
                const __nv_bfloat16* p = Ab + krow * 136 + mcol;
                ldsm_x4_t(a[mi][0], a[mi][1], a[mi][2], a[mi][3], cvta_s(p));
            }
            #pragma unroll
            for (int ni = 0; ni < 4; ni++) {
                const __nv_bfloat16* p = Bb + (ks * 16 + (lane & 15)) * 136
                                            + wn * 32 + ni * 8;
                ldsm_x2_t(bf[ni][0], bf[ni][1], cvta_s(p));
            }
            #pragma unroll
            for (int mi = 0; mi < 4; mi++)
                #pragma unroll
                for (int ni = 0; ni < 4; ni++)
                    mma_bf16(acc[mi][ni], a[mi], bf[ni]);
        }
        __syncthreads();
    }
    #pragma unroll
    for (int mi = 0; mi < 4; mi++)
        #pragma unroll
        for (int ni = 0; ni < 4; ni++) {
            int row = m0 + wm * 64 + mi * 16 + (lane >> 2);
            int col = n0 + wn * 32 + ni * 8 + (lane & 3) * 2;
            float b0 = bias[col], b1 = bias[col + 1];
            *(float2*)&out[(size_t)row * Fq + col] =
                make_float2(acc[mi][ni][0] + b0, acc[mi][ni][1] + b1);
            *(float2*)&out[(size_t)(row + 8) * Fq + col] =
                make_float2(acc[mi][ni][2] + b0, acc[mi][ni][3] + b1);
        }
}

// ---------------- launch -----------------------------------------------------
extern "C" void kernel_launch(void* const* d_in, const int* in_sizes, int n_in,
                              void* d_out, int out_size) {
    const float* u      = (const float*)d_in[0];
    const float* h      = (const float*)d_in[1];
    const float* bias   = (const float*)d_in[2];
    const float* w_in   = (const float*)d_in[3];
    const float* b_in   = (const float*)d_in[4];
    const float* conv_k = (const float*)d_in[5];
    const float* conv_b = (const float*)d_in[6];
    const float* w_out  = (const float*)d_in[7];
    const float* b_out  = (const float*)d_in[8];
    float* out = (float*)d_out;

    const int fft_smem  = FFT_SMEM_FLOATS * 2 * sizeof(float);   // 139264
    const int up_smem   = (2 * 9216 + 2 * 8704) * 2;             // 71680
    const int outp_smem = (2 * 8704 + 2 * 8704) * 2;             // 69632
    cudaFuncSetAttribute(hfft_kernel,  cudaFuncAttributeMaxDynamicSharedMemorySize, fft_smem);
    cudaFuncSetAttribute(chain_kernel, cudaFuncAttributeMaxDynamicSharedMemorySize, fft_smem);
    cudaFuncSetAttribute(gemm_up_tc,   cudaFuncAttributeMaxDynamicSharedMemorySize, up_smem);
    cudaFuncSetAttribute(gemm_out_tc,  cudaFuncAttributeMaxDynamicSharedMemorySize, outp_smem);

    __nv_bfloat16 *uh, *ul, *wih, *wil, *woh, *wol;
    cudaGetSymbolAddress((void**)&uh,  g_uh);
    cudaGetSymbolAddress((void**)&ul,  g_ul);
    cudaGetSymbolAddress((void**)&wih, g_wih);
    cudaGetSymbolAddress((void**)&wil, g_wil);
    cudaGetSymbolAddress((void**)&woh, g_woh);
    cudaGetSymbolAddress((void**)&wol, g_wol);

    cvt_split<<<(Mq * Fq) / 256, 256>>>(u, uh, ul, Mq * Fq);
    cvt_split<<<(Fq * IWq) / 256, 256>>>(w_in, wih, wil, Fq * IWq);
    cvt_split<<<(Fq * Fq) / 256, 256>>>(w_out, woh, wol, Fq * Fq);
    transpose_h<<<dim3(Fq / 32, Lq / 32, 2), dim3(32, 8)>>>(h);

    gemm_up_tc<<<dim3(IWq / 128, Mq / 128), 256, up_smem>>>(b_in);
    conv_gate<<<dim3(Fq / 32, Lq / 32, Bq), 256>>>(conv_k, conv_b);
    hfft_kernel<<<Fq, 512, fft_smem>>>();
    chain_kernel<<<Bq * Fq / 2, 512, fft_smem>>>(bias);
    gemm_out_tc<<<dim3(Fq / 128, Mq / 128), 256, outp_smem>>>(b_out, out);
}